// round 4
// baseline (speedup 1.0000x reference)
#include <cuda_runtime.h>

// Problem constants (fixed shapes from reference):
//   x : (2, 128, 96, 96) f32, w{q,k,v} : (4, 32, 32) f32
//   K = 5 window, reflect pad 2, G = 4 groups of 32 channels.
#define BB   2
#define GG   4
#define CIN  32
#define CON  32
#define HHN  96
#define WWN  96
#define HWSZ (HHN * WWN)
#define CTOT 128

// Scratch for the three 1x1-conv outputs (q, k, v), each (B, 128, 96, 96).
__device__ __align__(256) float g_q[BB * CTOT * HWSZ];
__device__ __align__(256) float g_k[BB * CTOT * HWSZ];
__device__ __align__(256) float g_v[BB * CTOT * HWSZ];

// -----------------------------------------------------------------------------
// Kernel A: grouped 1x1 convs (q, k, v) fused — one CTA per (b, g, h) row.
// smem: x row tile (32 ch x 96 w) + the group's 3 weight matrices (stride 33
// to avoid bank conflicts). Each thread owns one output channel o and a
// 12-wide w segment; 36 register accumulators -> 36 FMA per i-step vs 4 LDS.
// -----------------------------------------------------------------------------
__global__ __launch_bounds__(256) void qkv_kernel(
    const float* __restrict__ x,
    const float* __restrict__ wq,
    const float* __restrict__ wk,
    const float* __restrict__ wv)
{
    __shared__ float xs[CIN * WWN];            // 12 KB
    __shared__ float wqs[CON * 33];            // padded stride 33
    __shared__ float wks[CON * 33];
    __shared__ float wvs[CON * 33];

    const int h   = blockIdx.x;
    const int bg  = blockIdx.y;                // b*G + g
    const int g   = bg & (GG - 1);
    const int tid = threadIdx.x;

    // Stage x row: x[bg*32 + i][h][w]
    const float* xbase = x + (size_t)bg * CIN * HWSZ + (size_t)h * WWN;
    #pragma unroll
    for (int idx = tid; idx < CIN * WWN; idx += 256) {
        int i = idx / WWN;
        int w = idx - i * WWN;
        xs[idx] = xbase[(size_t)i * HWSZ + w];
    }
    // Stage weights of this group
    const float* wqg = wq + (size_t)g * CON * CIN;
    const float* wkg = wk + (size_t)g * CON * CIN;
    const float* wvg = wv + (size_t)g * CON * CIN;
    #pragma unroll
    for (int idx = tid; idx < CON * CIN; idx += 256) {
        int o = idx >> 5;
        int i = idx & 31;
        wqs[o * 33 + i] = wqg[idx];
        wks[o * 33 + i] = wkg[idx];
        wvs[o * 33 + i] = wvg[idx];
    }
    __syncthreads();

    const int o    = tid >> 3;            // 0..31 output channel
    const int wseg = (tid & 7) * 12;      // 12 consecutive w positions

    float aq[12], ak[12], av[12];
    #pragma unroll
    for (int u = 0; u < 12; u++) { aq[u] = 0.f; ak[u] = 0.f; av[u] = 0.f; }

    #pragma unroll 8
    for (int i = 0; i < CIN; i++) {
        const float wqv = wqs[o * 33 + i];
        const float wkv = wks[o * 33 + i];
        const float wvv = wvs[o * 33 + i];
        const float4* xv = reinterpret_cast<const float4*>(&xs[i * WWN + wseg]);
        float4 x0 = xv[0], x1 = xv[1], x2 = xv[2];
        float xr[12] = { x0.x, x0.y, x0.z, x0.w,
                         x1.x, x1.y, x1.z, x1.w,
                         x2.x, x2.y, x2.z, x2.w };
        #pragma unroll
        for (int u = 0; u < 12; u++) {
            aq[u] = fmaf(xr[u], wqv, aq[u]);
            ak[u] = fmaf(xr[u], wkv, ak[u]);
            av[u] = fmaf(xr[u], wvv, av[u]);
        }
    }

    const size_t obase = (size_t)(bg * CON + o) * HWSZ + (size_t)h * WWN + wseg;
    float4* qo = reinterpret_cast<float4*>(&g_q[obase]);
    float4* ko = reinterpret_cast<float4*>(&g_k[obase]);
    float4* vo = reinterpret_cast<float4*>(&g_v[obase]);
    #pragma unroll
    for (int u = 0; u < 3; u++) {
        qo[u] = make_float4(aq[4*u], aq[4*u+1], aq[4*u+2], aq[4*u+3]);
        ko[u] = make_float4(ak[4*u], ak[4*u+1], ak[4*u+2], ak[4*u+3]);
        vo[u] = make_float4(av[4*u], av[4*u+1], av[4*u+2], av[4*u+3]);
    }
}

// -----------------------------------------------------------------------------
// Kernel B: per-channel 5x5 windowed softmax with reflect indexing.
// One CTA = 16x16 spatial tile x 8 channels. k/v 20x20 halos staged in smem
// (25.6 KB) -> each halo value read from GMEM once, reused 25x from smem.
// Single-pass softmax (no max subtraction; |q*k| is small by construction,
// so exp stays far from fp32 overflow).
// -----------------------------------------------------------------------------
__device__ __forceinline__ int refl(int i, int n) {
    return i < 0 ? -i : (i >= n ? 2 * n - 2 - i : i);
}

__global__ __launch_bounds__(256) void attn_kernel(float* __restrict__ out)
{
    __shared__ float ks[8 * 400];   // 8 ch x 20 x 20
    __shared__ float vs[8 * 400];

    const int b_cc = blockIdx.z;               // b*16 + channel-chunk
    const int h0   = blockIdx.y * 16;
    const int w0   = blockIdx.x * 16;
    const int tx   = threadIdx.x;
    const int ty   = threadIdx.y;
    const int tid  = ty * 16 + tx;

    const size_t chunk_base = (size_t)b_cc * 8 * HWSZ;

    // Stage k/v halos for all 8 channels (reflect at global borders).
    #pragma unroll
    for (int idx = tid; idx < 8 * 400; idx += 256) {
        int ch  = idx / 400;
        int pos = idx - ch * 400;
        int r   = pos / 20;
        int c   = pos - r * 20;
        int hh  = refl(h0 - 2 + r, HHN);
        int ww  = refl(w0 - 2 + c, WWN);
        size_t gi = chunk_base + (size_t)ch * HWSZ + (size_t)hh * WWN + ww;
        ks[idx] = g_k[gi];
        vs[idx] = g_v[gi];
    }
    __syncthreads();

    const int h = h0 + ty;
    const int w = w0 + tx;
    const size_t pix = (size_t)h * WWN + w;

    for (int ch = 0; ch < 8; ch++) {
        const float qv = g_q[chunk_base + (size_t)ch * HWSZ + pix];
        const float* kp = &ks[ch * 400 + ty * 20 + tx];
        const float* vp = &vs[ch * 400 + ty * 20 + tx];
        float num = 0.f, den = 0.f;
        #pragma unroll
        for (int r = 0; r < 5; r++) {
            #pragma unroll
            for (int c = 0; c < 5; c++) {
                float e = __expf(qv * kp[r * 20 + c]);
                den += e;
                num = fmaf(e, vp[r * 20 + c], num);
            }
        }
        out[chunk_base + (size_t)ch * HWSZ + pix] = __fdividef(num, den);
    }
}

// -----------------------------------------------------------------------------
// Launch: two kernels, graph-capturable (no sync, no alloc).
// Inputs (metadata order): x, wq, wk, wv — all float32. Output float32.
// -----------------------------------------------------------------------------
extern "C" void kernel_launch(void* const* d_in, const int* in_sizes, int n_in,
                              void* d_out, int out_size)
{
    const float* x  = (const float*)d_in[0];
    const float* wq = (const float*)d_in[1];
    const float* wk = (const float*)d_in[2];
    const float* wv = (const float*)d_in[3];
    float* out = (float*)d_out;

    qkv_kernel<<<dim3(HHN, BB * GG), 256>>>(x, wq, wk, wv);
    attn_kernel<<<dim3(WWN / 16, HHN / 16, BB * (CTOT / 8)), dim3(16, 16)>>>(out);
}

// round 5
// speedup vs baseline: 1.5353x; 1.5353x over previous
#include <cuda_runtime.h>

// Problem constants (fixed shapes from reference):
//   x : (2, 128, 96, 96) f32, w{q,k,v} : (4, 32, 32) f32
//   K = 5 window, reflect pad 2, G = 4 groups of 32 channels.
#define BB   2
#define GG   4
#define CIN  32
#define CON  32
#define HHN  96
#define WWN  96
#define HWSZ (HHN * WWN)
#define CTOT 128

// Scratch for the three 1x1-conv outputs (q, k, v), each (B, 128, 96, 96).
__device__ __align__(256) float g_q[BB * CTOT * HWSZ];
__device__ __align__(256) float g_k[BB * CTOT * HWSZ];
__device__ __align__(256) float g_v[BB * CTOT * HWSZ];

// -----------------------------------------------------------------------------
// Kernel A: grouped 1x1 convs (q, k, v) fused — one CTA per (b, g, h) row.
// Forced occupancy 2 so 16 warps/SM hide the smem-load latency in the mainloop.
// -----------------------------------------------------------------------------
__global__ __launch_bounds__(256, 2) void qkv_kernel(
    const float* __restrict__ x,
    const float* __restrict__ wq,
    const float* __restrict__ wk,
    const float* __restrict__ wv)
{
    __shared__ float xs[CIN * WWN];            // 12 KB
    __shared__ float wqs[CON * 33];            // padded stride 33
    __shared__ float wks[CON * 33];
    __shared__ float wvs[CON * 33];

    const int h   = blockIdx.x;
    const int bg  = blockIdx.y;                // b*G + g
    const int g   = bg & (GG - 1);
    const int tid = threadIdx.x;

    // Stage x row: x[bg*32 + i][h][w]
    const float* xbase = x + (size_t)bg * CIN * HWSZ + (size_t)h * WWN;
    #pragma unroll
    for (int idx = tid; idx < CIN * WWN; idx += 256) {
        int i = idx / WWN;
        int w = idx - i * WWN;
        xs[idx] = xbase[(size_t)i * HWSZ + w];
    }
    // Stage weights of this group
    const float* wqg = wq + (size_t)g * CON * CIN;
    const float* wkg = wk + (size_t)g * CON * CIN;
    const float* wvg = wv + (size_t)g * CON * CIN;
    #pragma unroll
    for (int idx = tid; idx < CON * CIN; idx += 256) {
        int o = idx >> 5;
        int i = idx & 31;
        wqs[o * 33 + i] = wqg[idx];
        wks[o * 33 + i] = wkg[idx];
        wvs[o * 33 + i] = wvg[idx];
    }
    __syncthreads();

    const int o    = tid >> 3;            // 0..31 output channel
    const int wseg = (tid & 7) * 12;      // 12 consecutive w positions

    float aq[12], ak[12], av[12];
    #pragma unroll
    for (int u = 0; u < 12; u++) { aq[u] = 0.f; ak[u] = 0.f; av[u] = 0.f; }

    #pragma unroll 8
    for (int i = 0; i < CIN; i++) {
        const float wqv = wqs[o * 33 + i];
        const float wkv = wks[o * 33 + i];
        const float wvv = wvs[o * 33 + i];
        const float4* xv = reinterpret_cast<const float4*>(&xs[i * WWN + wseg]);
        float4 x0 = xv[0], x1 = xv[1], x2 = xv[2];
        float xr[12] = { x0.x, x0.y, x0.z, x0.w,
                         x1.x, x1.y, x1.z, x1.w,
                         x2.x, x2.y, x2.z, x2.w };
        #pragma unroll
        for (int u = 0; u < 12; u++) {
            aq[u] = fmaf(xr[u], wqv, aq[u]);
            ak[u] = fmaf(xr[u], wkv, ak[u]);
            av[u] = fmaf(xr[u], wvv, av[u]);
        }
    }

    const size_t obase = (size_t)(bg * CON + o) * HWSZ + (size_t)h * WWN + wseg;
    float4* qo = reinterpret_cast<float4*>(&g_q[obase]);
    float4* ko = reinterpret_cast<float4*>(&g_k[obase]);
    float4* vo = reinterpret_cast<float4*>(&g_v[obase]);
    #pragma unroll
    for (int u = 0; u < 3; u++) {
        qo[u] = make_float4(aq[4*u], aq[4*u+1], aq[4*u+2], aq[4*u+3]);
        ko[u] = make_float4(ak[4*u], ak[4*u+1], ak[4*u+2], ak[4*u+3]);
        vo[u] = make_float4(av[4*u], av[4*u+1], av[4*u+2], av[4*u+3]);
    }
}

// -----------------------------------------------------------------------------
// Kernel B: per-channel 5x5 windowed softmax with reflect indexing.
// One CTA = 32x32 spatial tile x 1 channel. Each thread computes 4 consecutive
// w outputs: adjacent windows share 4/5 columns, so only 8 k + 8 v smem loads
// per window row serve 4 outputs (20 LDS/output vs 50 before).
// Halo stride 41 (== 9 mod 32): bank = 9*ty + 4*tx + j is a permutation over
// the warp's 4(ty) x 8(tx) layout -> conflict-free scalar LDS.
// Single-pass softmax via raw ex2.approx (log2e folded into q).
// -----------------------------------------------------------------------------
__device__ __forceinline__ int refl(int i, int n) {
    return i < 0 ? -i : (i >= n ? 2 * n - 2 - i : i);
}

__device__ __forceinline__ float ex2(float x) {
    float y;
    asm("ex2.approx.ftz.f32 %0, %1;" : "=f"(y) : "f"(x));
    return y;
}

#define HALO 36
#define HSTR 41

__global__ __launch_bounds__(256) void attn_kernel(float* __restrict__ out)
{
    __shared__ float ks[HALO * HSTR];   // 5.9 KB
    __shared__ float vs[HALO * HSTR];

    const int ch  = blockIdx.z;               // 0..255 = b*128 + channel
    const int h0  = blockIdx.y * 32;
    const int w0  = blockIdx.x * 32;
    const int tid = threadIdx.x;
    const int tx  = tid & 7;                  // 8 threads across w (4 outputs each)
    const int ty  = tid >> 3;                 // 32 rows

    const size_t cbase = (size_t)ch * HWSZ;

    // Stage k/v halos (36x36 window, reflect at global borders).
    #pragma unroll
    for (int idx = tid; idx < HALO * HALO; idx += 256) {
        int r  = idx / HALO;
        int c  = idx - r * HALO;
        int hh = refl(h0 - 2 + r, HHN);
        int ww = refl(w0 - 2 + c, WWN);
        size_t gi = cbase + (size_t)hh * WWN + ww;
        ks[r * HSTR + c] = g_k[gi];
        vs[r * HSTR + c] = g_v[gi];
    }
    __syncthreads();

    const int h    = h0 + ty;
    const int wsub = tx * 4;                  // halo column base for this thread
    const size_t pix = (size_t)h * WWN + (w0 + wsub);

    const float4 q4 = *reinterpret_cast<const float4*>(&g_q[cbase + pix]);
    const float L2E = 1.44269504088896341f;
    float ql2[4] = { q4.x * L2E, q4.y * L2E, q4.z * L2E, q4.w * L2E };

    float num[4] = {0.f, 0.f, 0.f, 0.f};
    float den[4] = {0.f, 0.f, 0.f, 0.f};

    #pragma unroll
    for (int r = 0; r < 5; r++) {
        const float* kp = &ks[(ty + r) * HSTR + wsub];
        const float* vp = &vs[(ty + r) * HSTR + wsub];
        float kk[8], vv[8];
        #pragma unroll
        for (int j = 0; j < 8; j++) { kk[j] = kp[j]; vv[j] = vp[j]; }
        #pragma unroll
        for (int o = 0; o < 4; o++) {
            #pragma unroll
            for (int c = 0; c < 5; c++) {
                float e = ex2(ql2[o] * kk[o + c]);
                den[o] += e;
                num[o] = fmaf(e, vv[o + c], num[o]);
            }
        }
    }

    float4 r4 = make_float4(__fdividef(num[0], den[0]),
                            __fdividef(num[1], den[1]),
                            __fdividef(num[2], den[2]),
                            __fdividef(num[3], den[3]));
    *reinterpret_cast<float4*>(&out[cbase + pix]) = r4;
}

// -----------------------------------------------------------------------------
// Launch: two kernels, graph-capturable (no sync, no alloc).
// Inputs (metadata order): x, wq, wk, wv — all float32. Output float32.
// -----------------------------------------------------------------------------
extern "C" void kernel_launch(void* const* d_in, const int* in_sizes, int n_in,
                              void* d_out, int out_size)
{
    const float* x  = (const float*)d_in[0];
    const float* wq = (const float*)d_in[1];
    const float* wk = (const float*)d_in[2];
    const float* wv = (const float*)d_in[3];
    float* out = (float*)d_out;

    qkv_kernel<<<dim3(HHN, BB * GG), 256>>>(x, wq, wk, wv);
    attn_kernel<<<dim3(WWN / 32, HHN / 32, BB * CTOT), dim3(256)>>>(out);
}